// round 7
// baseline (speedup 1.0000x reference)
#include <cuda_runtime.h>
#include <cstdint>

// Problem constants
#define Bn 4
#define Ln 512
#define Hn 768
#define En 10
#define Rn 10

#define BK 32
#define SROW 36   // padded row stride (floats): (4g+t) mod 32 distinct -> conflict-free frags

// ---------------- scratch (device globals: allocation-guard safe) ----------
__device__ float g_hr[Bn * Ln * Hn];        // rounded h
__device__ float g_wpr[Hn * Hn];            // rounded W_proj
__device__ float g_wbr[Rn * Hn * Hn];       // rounded W_bil
__device__ float g_hproj[Bn * Ln * Hn];     // hproj (tf32-rounded)
__device__ float g_t[Bn * Rn * Ln * Hn];    // t (tf32-rounded)

// ---------------- helpers ----------------------------------------------------
__device__ __forceinline__ uint32_t smem_u32(const void* p) {
    uint32_t a;
    asm("{ .reg .u64 t; cvta.to.shared.u64 t, %1; cvt.u32.u64 %0, t; }" : "=r"(a) : "l"(p));
    return a;
}

__device__ __forceinline__ void cp16(uint32_t saddr, const void* g) {
    asm volatile("cp.async.cg.shared.global [%0], [%1], 16;" :: "r"(saddr), "l"(g));
}
#define CP_COMMIT() asm volatile("cp.async.commit_group;" ::: "memory")
#define CP_WAIT1()  asm volatile("cp.async.wait_group 1;" ::: "memory")

__device__ __forceinline__ float rtf32(float x) {
    uint32_t u;
    asm("cvt.rna.tf32.f32 %0, %1;" : "=r"(u) : "f"(x));
    return __uint_as_float(u);
}

__device__ __forceinline__ void mma8(float* c, const uint32_t* a, const uint32_t* b) {
    asm volatile(
        "mma.sync.aligned.m16n8k8.row.col.f32.tf32.tf32.f32 "
        "{%0,%1,%2,%3}, {%4,%5,%6,%7}, {%8,%9}, {%0,%1,%2,%3};"
        : "+f"(c[0]), "+f"(c[1]), "+f"(c[2]), "+f"(c[3])
        : "r"(a[0]), "r"(a[1]), "r"(a[2]), "r"(a[3]), "r"(b[0]), "r"(b[1]));
}

__device__ __forceinline__ uint32_t lds32(uint32_t addr) {
    uint32_t v;
    asm volatile("ld.shared.b32 %0, [%1];" : "=r"(v) : "r"(addr));
    return v;
}

// ---------------- tf32 mma.sync GEMM (templated config) ------------------------
// C[row, col] = sum_k A[za][row,k] * B[zb][col,k]   (A,B both K-major)
// za = z / 10, zb = z % bZmod
// C addr: C + (z/10)*cZ1 + (z%10)*cZ2 + row*sCm + col*sCn
// mode: 1=relu, 2=round-to-tf32, 4=bias[col], 8=bias[z%10]
// Warp layout: 4 warps along N; warp tile = 64 x (BN_/4).
template <int BM_, int BN_, int NTHR_, int MAXCTA_, bool PIPE_>
__global__ void __launch_bounds__(NTHR_, MAXCTA_) gemm_mma(
    const float* __restrict__ A, long sAz,
    const float* __restrict__ B, int bZmod, long sBz,
    float* __restrict__ C, long cZ1, long cZ2, long sCm, long sCn,
    const float* __restrict__ bias, int mode, int K)
{
    constexpr int WN = BN_ / 4;          // warp N extent
    constexpr int NI = WN / 8;           // n8-tiles per warp
    constexpr int ABYT = BM_ * SROW * 4;
    constexpr int STG = ABYT + BN_ * SROW * 4;
    constexpr int RPP = NTHR_ / 8;       // rows per cp.async pass

    extern __shared__ __align__(16) char smem[];
    const uint32_t sbase = smem_u32(smem);
    const int tid = threadIdx.x;
    const int z = blockIdx.z;
    const int m0 = blockIdx.y * BM_;
    const int n0 = blockIdx.x * BN_;
    const int nk = K / BK;

    const float* Ag = A + (long)(z / 10) * sAz + (long)m0 * K;
    const float* Bg = B + (long)(z % bZmod) * sBz + (long)n0 * K;

    const int wid = tid >> 5;
    const int lane = tid & 31;
    const int warp_m = wid >> 2;         // 64-row blocks
    const int warp_n = wid & 3;          // WN-col blocks
    const int g = lane >> 2;
    const int t = lane & 3;

    float acc[4][NI][4];
#pragma unroll
    for (int mi = 0; mi < 4; ++mi)
#pragma unroll
        for (int ni = 0; ni < NI; ++ni)
#pragma unroll
            for (int q = 0; q < 4; ++q) acc[mi][ni][q] = 0.0f;

    // per-thread cp.async source/dest (reused every stage)
    const int ld_row = tid >> 3;               // 0..RPP-1
    const int ld_seg = (tid & 7) * 4;
    const float* AgT = Ag + (long)ld_row * K + ld_seg;
    const float* BgT = Bg + (long)ld_row * K + ld_seg;
    const uint32_t sOffT = (uint32_t)(ld_row * SROW + ld_seg) * 4;
    const uint32_t rowStepS = (uint32_t)RPP * SROW * 4u;

    auto load_stage = [&](int s, int k0) {
        const uint32_t sA = sbase + s * STG + sOffT;
        const uint32_t sB = sA + ABYT;
#pragma unroll
        for (int it = 0; it < BM_ / RPP; ++it)
            cp16(sA + it * rowStepS, AgT + (long)(it * RPP) * K + k0);
#pragma unroll
        for (int it = 0; it < BN_ / RPP; ++it)
            cp16(sB + it * rowStepS, BgT + (long)(it * RPP) * K + k0);
    };

    load_stage(0, 0); CP_COMMIT();
    if (nk > 1) load_stage(1, BK);
    CP_COMMIT();

    const uint32_t aBase = (uint32_t)((warp_m * 64 + g) * SROW + t) * 4;
    const uint32_t bBase = (uint32_t)((warp_n * WN + g) * SROW + t) * 4;

#define LOAD_FRAGS(dstA, dstB, ks)                                              \
    do {                                                                        \
        _Pragma("unroll")                                                       \
        for (int mi = 0; mi < 4; ++mi) {                                        \
            const uint32_t p = sA + aBase + (uint32_t)(mi * 16 * SROW + (ks)) * 4; \
            (dstA)[mi][0] = lds32(p);                                           \
            (dstA)[mi][1] = lds32(p + 8 * SROW * 4);                            \
            (dstA)[mi][2] = lds32(p + 16);                                      \
            (dstA)[mi][3] = lds32(p + 8 * SROW * 4 + 16);                       \
        }                                                                       \
        _Pragma("unroll")                                                       \
        for (int ni = 0; ni < NI; ++ni) {                                       \
            const uint32_t p = sB + bBase + (uint32_t)(ni * 8 * SROW + (ks)) * 4;  \
            (dstB)[ni][0] = lds32(p);                                           \
            (dstB)[ni][1] = lds32(p + 16);                                      \
        }                                                                       \
    } while (0)

    for (int i = 0; i < nk; ++i) {
        CP_WAIT1();
        __syncthreads();
        if (i + 2 < nk) load_stage((i + 2) % 3, (i + 2) * BK);
        CP_COMMIT();

        const uint32_t sA = sbase + (i % 3) * STG;
        const uint32_t sB = sA + ABYT;

        if (PIPE_) {
            // software-pipelined fragments: LDS(ks+1) issued before MMA(ks)
            uint32_t af[2][4][4], bf[2][NI][2];
            LOAD_FRAGS(af[0], bf[0], 0);
#pragma unroll
            for (int ks8 = 0; ks8 < BK / 8; ++ks8) {
                const int cur = ks8 & 1;
                if (ks8 + 1 < BK / 8) LOAD_FRAGS(af[cur ^ 1], bf[cur ^ 1], (ks8 + 1) * 8);
#pragma unroll
                for (int mi = 0; mi < 4; ++mi)
#pragma unroll
                    for (int ni = 0; ni < NI; ++ni)
                        mma8(acc[mi][ni], af[cur][mi], bf[cur][ni]);
            }
        } else {
#pragma unroll
            for (int ks8 = 0; ks8 < BK / 8; ++ks8) {
                uint32_t af[4][4], bf[NI][2];
                LOAD_FRAGS(af, bf, ks8 * 8);
#pragma unroll
                for (int mi = 0; mi < 4; ++mi)
#pragma unroll
                    for (int ni = 0; ni < NI; ++ni)
                        mma8(acc[mi][ni], af[mi], bf[ni]);
            }
        }
    }
#undef LOAD_FRAGS

    // ---------------- epilogue ----------------
    float bz = 0.0f;
    if (mode & 8) bz = bias[z % 10];
    float* Cz = C + (long)(z / 10) * cZ1 + (long)(z % 10) * cZ2;

#pragma unroll
    for (int mi = 0; mi < 4; ++mi) {
        const long r0 = m0 + warp_m * 64 + mi * 16 + g;
#pragma unroll
        for (int ni = 0; ni < NI; ++ni) {
            const long col = n0 + warp_n * WN + ni * 8 + 2 * t;
            float v[4];
#pragma unroll
            for (int q = 0; q < 4; ++q) v[q] = acc[mi][ni][q];
            if (mode & 4) {
                const float b0v = bias[col], b1v = bias[col + 1];
                v[0] += b0v; v[1] += b1v; v[2] += b0v; v[3] += b1v;
            }
            if (mode & 8) { v[0] += bz; v[1] += bz; v[2] += bz; v[3] += bz; }
            if (mode & 1) {
#pragma unroll
                for (int q = 0; q < 4; ++q) v[q] = fmaxf(v[q], 0.0f);
            }
            if (mode & 2) {
#pragma unroll
                for (int q = 0; q < 4; ++q) v[q] = rtf32(v[q]);
            }
            if (sCn == 1) {
                *(float2*)(Cz + r0 * sCm + col) = make_float2(v[0], v[1]);
                *(float2*)(Cz + (r0 + 8) * sCm + col) = make_float2(v[2], v[3]);
            } else {
                float* p0 = Cz + r0 * sCm + col * sCn;
                float* p1 = Cz + (r0 + 8) * sCm + col * sCn;
                p0[0] = v[0]; p0[sCn] = v[1];
                p1[0] = v[2]; p1[sCn] = v[3];
            }
        }
    }
}

// ---------------- round-to-tf32 pre-pass -------------------------------------
__global__ void round_k(const float4* __restrict__ in, float4* __restrict__ out, int n4) {
    int i = blockIdx.x * blockDim.x + threadIdx.x;
    if (i < n4) {
        float4 a = in[i];
        a.x = rtf32(a.x); a.y = rtf32(a.y); a.z = rtf32(a.z); a.w = rtf32(a.w);
        out[i] = a;
    }
}

// ---------------- entity head (fp32 FFMA, tiny) -------------------------------
__global__ __launch_bounds__(256) void ent_kernel(
    const float* __restrict__ hproj, const float* __restrict__ W_ent,
    const float* __restrict__ b_ent, float* __restrict__ out)
{
    const int warp = threadIdx.x >> 5;
    const int lane = threadIdx.x & 31;
    const int row = blockIdx.x * 8 + warp;
    const float* hp = hproj + (long)row * Hn;

    float acc[En];
#pragma unroll
    for (int e = 0; e < En; ++e) acc[e] = 0.0f;
    for (int k = lane; k < Hn; k += 32) {
        const float hv = hp[k];
#pragma unroll
        for (int e = 0; e < En; ++e) acc[e] = fmaf(hv, W_ent[e * Hn + k], acc[e]);
    }
#pragma unroll
    for (int e = 0; e < En; ++e)
#pragma unroll
        for (int o = 16; o > 0; o >>= 1)
            acc[e] += __shfl_xor_sync(0xffffffffu, acc[e], o);
    if (lane == 0) {
        float* o = out + (long)row * En;
#pragma unroll
        for (int e = 0; e < En; ++e) o[e] = acc[e] + b_ent[e];
    }
}

// ---------------- host --------------------------------------------------------
// config A: proj     128x128, 256 thr, 2 CTA/SM, no frag pipe  (smem 110592)
// config B: stages   256x256, 512 thr, 1 CTA/SM, frag pipe     (smem 221184)
#define SMEM_A_CFG (3 * (128 + 128) * SROW * 4)
#define SMEM_B_CFG (3 * (256 + 256) * SROW * 4)

extern "C" void kernel_launch(void* const* d_in, const int* in_sizes, int n_in,
                              void* d_out, int out_size)
{
    const float* h      = (const float*)d_in[0];
    const float* W_proj = (const float*)d_in[1];
    const float* b_proj = (const float*)d_in[2];
    const float* W_ent  = (const float*)d_in[3];
    const float* b_ent  = (const float*)d_in[4];
    const float* W_bil  = (const float*)d_in[5];
    const float* b_bil  = (const float*)d_in[6];
    float* out = (float*)d_out;

    float *hr, *wpr, *wbr, *hproj, *tbuf;
    cudaGetSymbolAddress((void**)&hr, g_hr);
    cudaGetSymbolAddress((void**)&wpr, g_wpr);
    cudaGetSymbolAddress((void**)&wbr, g_wbr);
    cudaGetSymbolAddress((void**)&hproj, g_hproj);
    cudaGetSymbolAddress((void**)&tbuf, g_t);

    auto kA = gemm_mma<128, 128, 256, 2, false>;
    auto kB = gemm_mma<256, 256, 512, 1, true>;
    cudaFuncSetAttribute(kA, cudaFuncAttributeMaxDynamicSharedMemorySize, SMEM_A_CFG);
    cudaFuncSetAttribute(kB, cudaFuncAttributeMaxDynamicSharedMemorySize, SMEM_B_CFG);

    // 0) round inputs to nearest-tf32 (zero-mean rounding error)
    {
        int n4;
        n4 = Bn * Ln * Hn / 4;  round_k<<<(n4 + 255) / 256, 256>>>((const float4*)h, (float4*)hr, n4);
        n4 = Hn * Hn / 4;       round_k<<<(n4 + 255) / 256, 256>>>((const float4*)W_proj, (float4*)wpr, n4);
        n4 = Rn * Hn * Hn / 4;  round_k<<<(n4 + 255) / 256, 256>>>((const float4*)W_bil, (float4*)wbr, n4);
    }

    const long entOff = (long)Bn * Ln * En;  // 20480

    // 1) hproj = rtf32(relu(h @ W_proj^T + b_proj))   M=2048 N=768 K=768
    {
        dim3 grid(Hn / 128, (Bn * Ln) / 128, 1);
        kA<<<grid, 256, SMEM_A_CFG>>>(
            hr, 0,
            wpr, 1, 0,
            hproj, 0, 0, (long)Hn, 1,
            b_proj, /*relu|round|biasN*/ 7, Hn);
    }

    // 2) ent_logits (fp32 FFMA)
    ent_kernel<<<(Bn * Ln) / 8, 256>>>(hproj, W_ent, b_ent, out);

    // 3) t[z] = rtf32(P_{z/10} @ W_bil[z%10]^T)   M=512 N=768 K=768, 40 batches
    {
        dim3 grid(Hn / 256, Ln / 256, Bn * Rn);
        kB<<<grid, 512, SMEM_B_CFG>>>(
            hproj, (long)Ln * Hn,
            wbr, Rn, (long)Hn * Hn,
            tbuf, (long)Rn * Ln * Hn, (long)Ln * Hn, (long)Hn, 1,
            nullptr, /*round*/ 2, Hn);
    }

    // 4) rel[b,l,m,r] = P_b @ t[b,r]^T + b_bil[r]   M=512 N=512 K=768, 40 batches
    {
        dim3 grid(Ln / 256, Ln / 256, Bn * Rn);
        kB<<<grid, 512, SMEM_B_CFG>>>(
            hproj, (long)Ln * Hn,
            tbuf, Bn * Rn, (long)Ln * Hn,
            out + entOff, (long)Ln * Ln * Rn, 1, (long)Ln * Rn, (long)Rn,
            b_bil, /*biasZ*/ 8, Hn);
    }
}

// round 8
// speedup vs baseline: 2.3735x; 2.3735x over previous
#include <cuda_runtime.h>
#include <cstdint>

// Problem constants
#define Bn 4
#define Ln 512
#define Hn 768
#define En 10
#define Rn 10

#define BK 32
#define SROW 36   // padded row stride (floats): conflict-free fragment LDS

// ---------------- scratch (device globals: allocation-guard safe) ----------
__device__ float g_hr[Bn * Ln * Hn];        // rounded h
__device__ float g_wpr[Hn * Hn];            // rounded W_proj
__device__ float g_wbr[Rn * Hn * Hn];       // rounded W_bil
__device__ float g_hproj[Bn * Ln * Hn];     // hproj (tf32-rounded)
__device__ float g_t[Bn * Rn * Ln * Hn];    // t (tf32-rounded)

// ---------------- helpers ----------------------------------------------------
__device__ __forceinline__ uint32_t smem_u32(const void* p) {
    uint32_t a;
    asm("{ .reg .u64 t; cvta.to.shared.u64 t, %1; cvt.u32.u64 %0, t; }" : "=r"(a) : "l"(p));
    return a;
}

__device__ __forceinline__ void cp16(uint32_t saddr, const void* g) {
    asm volatile("cp.async.cg.shared.global [%0], [%1], 16;" :: "r"(saddr), "l"(g));
}
#define CP_COMMIT() asm volatile("cp.async.commit_group;" ::: "memory")
#define CP_WAIT1()  asm volatile("cp.async.wait_group 1;" ::: "memory")

__device__ __forceinline__ float rtf32(float x) {
    uint32_t u;
    asm("cvt.rna.tf32.f32 %0, %1;" : "=r"(u) : "f"(x));
    return __uint_as_float(u);
}

__device__ __forceinline__ void mma8(float* c, const uint32_t* a, const uint32_t* b) {
    asm volatile(
        "mma.sync.aligned.m16n8k8.row.col.f32.tf32.tf32.f32 "
        "{%0,%1,%2,%3}, {%4,%5,%6,%7}, {%8,%9}, {%0,%1,%2,%3};"
        : "+f"(c[0]), "+f"(c[1]), "+f"(c[2]), "+f"(c[3])
        : "r"(a[0]), "r"(a[1]), "r"(a[2]), "r"(a[3]), "r"(b[0]), "r"(b[1]));
}

__device__ __forceinline__ uint32_t lds32(uint32_t addr) {
    uint32_t v;
    asm volatile("ld.shared.b32 %0, [%1];" : "=r"(v) : "r"(addr));
    return v;
}

// ---------------- tf32 mma.sync GEMM (templated config) ------------------------
// C[row, col] = sum_k A[za][row,k] * B[zb][col,k]   (A,B both K-major)
// za = z / 10, zb = z % bZmod
// C addr: C + (z/10)*cZ1 + (z%10)*cZ2 + row*sCm + col*sCn
// mode: 1=relu, 2=round-to-tf32, 4=bias[col], 8=bias[z%10]
// Warp layout: warp_m = wid>>2 (64-row blocks), warp_n = wid&3 (32-col blocks)
// Every warp tile is 64x32 -> ~126 regs/thread, fits 128-reg cap at 512 thr.
template <int BM_, int BN_, int NTHR_, int MAXCTA_>
__global__ void __launch_bounds__(NTHR_, MAXCTA_) gemm_mma(
    const float* __restrict__ A, long sAz,
    const float* __restrict__ B, int bZmod, long sBz,
    float* __restrict__ C, long cZ1, long cZ2, long sCm, long sCn,
    const float* __restrict__ bias, int mode, int K)
{
    constexpr int ABYT = BM_ * SROW * 4;
    constexpr int STG = ABYT + BN_ * SROW * 4;
    constexpr int RPP = NTHR_ / 8;       // rows per cp.async pass

    extern __shared__ __align__(16) char smem[];
    const uint32_t sbase = smem_u32(smem);
    const int tid = threadIdx.x;
    const int z = blockIdx.z;
    const int m0 = blockIdx.y * BM_;
    const int n0 = blockIdx.x * BN_;
    const int nk = K / BK;

    const float* Ag = A + (long)(z / 10) * sAz + (long)m0 * K;
    const float* Bg = B + (long)(z % bZmod) * sBz + (long)n0 * K;

    const int wid = tid >> 5;
    const int lane = tid & 31;
    const int warp_m = wid >> 2;
    const int warp_n = wid & 3;
    const int g = lane >> 2;
    const int t = lane & 3;

    float acc[4][4][4];
#pragma unroll
    for (int mi = 0; mi < 4; ++mi)
#pragma unroll
        for (int ni = 0; ni < 4; ++ni)
#pragma unroll
            for (int q = 0; q < 4; ++q) acc[mi][ni][q] = 0.0f;

    // per-thread cp.async source/dest (reused every stage)
    const int ld_row = tid >> 3;
    const int ld_seg = (tid & 7) * 4;
    const float* AgT = Ag + (long)ld_row * K + ld_seg;
    const float* BgT = Bg + (long)ld_row * K + ld_seg;
    const uint32_t sOffT = (uint32_t)(ld_row * SROW + ld_seg) * 4;
    const uint32_t rowStepS = (uint32_t)RPP * SROW * 4u;

    auto load_stage = [&](int s, int k0) {
        const uint32_t sA = sbase + s * STG + sOffT;
        const uint32_t sB = sA + ABYT;
#pragma unroll
        for (int it = 0; it < BM_ / RPP; ++it)
            cp16(sA + it * rowStepS, AgT + (long)(it * RPP) * K + k0);
#pragma unroll
        for (int it = 0; it < BN_ / RPP; ++it)
            cp16(sB + it * rowStepS, BgT + (long)(it * RPP) * K + k0);
    };

    load_stage(0, 0); CP_COMMIT();
    if (nk > 1) load_stage(1, BK);
    CP_COMMIT();

    const uint32_t aBase = (uint32_t)((warp_m * 64 + g) * SROW + t) * 4;
    const uint32_t bBase = (uint32_t)((warp_n * 32 + g) * SROW + t) * 4;

    for (int i = 0; i < nk; ++i) {
        CP_WAIT1();
        __syncthreads();
        if (i + 2 < nk) load_stage((i + 2) % 3, (i + 2) * BK);
        CP_COMMIT();

        const uint32_t sA = sbase + (i % 3) * STG;
        const uint32_t sB = sA + ABYT;

#pragma unroll
        for (int ks = 0; ks < BK; ks += 8) {
            uint32_t af[4][4], bf[4][2];
#pragma unroll
            for (int mi = 0; mi < 4; ++mi) {
                const uint32_t p = sA + aBase + (uint32_t)(mi * 16 * SROW + ks) * 4;
                af[mi][0] = lds32(p);
                af[mi][1] = lds32(p + 8 * SROW * 4);
                af[mi][2] = lds32(p + 16);
                af[mi][3] = lds32(p + 8 * SROW * 4 + 16);
            }
#pragma unroll
            for (int ni = 0; ni < 4; ++ni) {
                const uint32_t p = sB + bBase + (uint32_t)(ni * 8 * SROW + ks) * 4;
                bf[ni][0] = lds32(p);
                bf[ni][1] = lds32(p + 16);
            }
#pragma unroll
            for (int mi = 0; mi < 4; ++mi)
#pragma unroll
                for (int ni = 0; ni < 4; ++ni)
                    mma8(acc[mi][ni], af[mi], bf[ni]);
        }
        __syncthreads();
    }

    // ---------------- epilogue ----------------
    float bz = 0.0f;
    if (mode & 8) bz = bias[z % 10];
    float* Cz = C + (long)(z / 10) * cZ1 + (long)(z % 10) * cZ2;

#pragma unroll
    for (int mi = 0; mi < 4; ++mi) {
        const long r0 = m0 + warp_m * 64 + mi * 16 + g;
#pragma unroll
        for (int ni = 0; ni < 4; ++ni) {
            const long col = n0 + warp_n * 32 + ni * 8 + 2 * t;
            float v[4];
#pragma unroll
            for (int q = 0; q < 4; ++q) v[q] = acc[mi][ni][q];
            if (mode & 4) {
                const float b0v = bias[col], b1v = bias[col + 1];
                v[0] += b0v; v[1] += b1v; v[2] += b0v; v[3] += b1v;
            }
            if (mode & 8) { v[0] += bz; v[1] += bz; v[2] += bz; v[3] += bz; }
            if (mode & 1) {
#pragma unroll
                for (int q = 0; q < 4; ++q) v[q] = fmaxf(v[q], 0.0f);
            }
            if (mode & 2) {
#pragma unroll
                for (int q = 0; q < 4; ++q) v[q] = rtf32(v[q]);
            }
            if (sCn == 1) {
                *(float2*)(Cz + r0 * sCm + col) = make_float2(v[0], v[1]);
                *(float2*)(Cz + (r0 + 8) * sCm + col) = make_float2(v[2], v[3]);
            } else {
                float* p0 = Cz + r0 * sCm + col * sCn;
                float* p1 = Cz + (r0 + 8) * sCm + col * sCn;
                p0[0] = v[0]; p0[sCn] = v[1];
                p1[0] = v[2]; p1[sCn] = v[3];
            }
        }
    }
}

// ---------------- round-to-tf32 pre-pass -------------------------------------
__global__ void round_k(const float4* __restrict__ in, float4* __restrict__ out, int n4) {
    int i = blockIdx.x * blockDim.x + threadIdx.x;
    if (i < n4) {
        float4 a = in[i];
        a.x = rtf32(a.x); a.y = rtf32(a.y); a.z = rtf32(a.z); a.w = rtf32(a.w);
        out[i] = a;
    }
}

// ---------------- entity head (fp32 FFMA, tiny) -------------------------------
__global__ __launch_bounds__(256) void ent_kernel(
    const float* __restrict__ hproj, const float* __restrict__ W_ent,
    const float* __restrict__ b_ent, float* __restrict__ out)
{
    const int warp = threadIdx.x >> 5;
    const int lane = threadIdx.x & 31;
    const int row = blockIdx.x * 8 + warp;
    const float* hp = hproj + (long)row * Hn;

    float acc[En];
#pragma unroll
    for (int e = 0; e < En; ++e) acc[e] = 0.0f;
    for (int k = lane; k < Hn; k += 32) {
        const float hv = hp[k];
#pragma unroll
        for (int e = 0; e < En; ++e) acc[e] = fmaf(hv, W_ent[e * Hn + k], acc[e]);
    }
#pragma unroll
    for (int e = 0; e < En; ++e)
#pragma unroll
        for (int o = 16; o > 0; o >>= 1)
            acc[e] += __shfl_xor_sync(0xffffffffu, acc[e], o);
    if (lane == 0) {
        float* o = out + (long)row * En;
#pragma unroll
        for (int e = 0; e < En; ++e) o[e] = acc[e] + b_ent[e];
    }
}

// ---------------- host --------------------------------------------------------
// config A: proj    128x128, 256 thr (8 warps, 2x4)   smem 110592
// config B: stages  256x128, 512 thr (16 warps, 4x4)  smem 165888
#define SMEM_A_CFG (3 * (128 + 128) * SROW * 4)
#define SMEM_B_CFG (3 * (256 + 128) * SROW * 4)

extern "C" void kernel_launch(void* const* d_in, const int* in_sizes, int n_in,
                              void* d_out, int out_size)
{
    const float* h      = (const float*)d_in[0];
    const float* W_proj = (const float*)d_in[1];
    const float* b_proj = (const float*)d_in[2];
    const float* W_ent  = (const float*)d_in[3];
    const float* b_ent  = (const float*)d_in[4];
    const float* W_bil  = (const float*)d_in[5];
    const float* b_bil  = (const float*)d_in[6];
    float* out = (float*)d_out;

    float *hr, *wpr, *wbr, *hproj, *tbuf;
    cudaGetSymbolAddress((void**)&hr, g_hr);
    cudaGetSymbolAddress((void**)&wpr, g_wpr);
    cudaGetSymbolAddress((void**)&wbr, g_wbr);
    cudaGetSymbolAddress((void**)&hproj, g_hproj);
    cudaGetSymbolAddress((void**)&tbuf, g_t);

    auto kA = gemm_mma<128, 128, 256, 2>;
    auto kB = gemm_mma<256, 128, 512, 1>;
    cudaFuncSetAttribute(kA, cudaFuncAttributeMaxDynamicSharedMemorySize, SMEM_A_CFG);
    cudaFuncSetAttribute(kB, cudaFuncAttributeMaxDynamicSharedMemorySize, SMEM_B_CFG);

    // 0) round inputs to nearest-tf32 (zero-mean rounding error)
    {
        int n4;
        n4 = Bn * Ln * Hn / 4;  round_k<<<(n4 + 255) / 256, 256>>>((const float4*)h, (float4*)hr, n4);
        n4 = Hn * Hn / 4;       round_k<<<(n4 + 255) / 256, 256>>>((const float4*)W_proj, (float4*)wpr, n4);
        n4 = Rn * Hn * Hn / 4;  round_k<<<(n4 + 255) / 256, 256>>>((const float4*)W_bil, (float4*)wbr, n4);
    }

    const long entOff = (long)Bn * Ln * En;  // 20480

    // 1) hproj = rtf32(relu(h @ W_proj^T + b_proj))   M=2048 N=768 K=768
    {
        dim3 grid(Hn / 128, (Bn * Ln) / 128, 1);
        kA<<<grid, 256, SMEM_A_CFG>>>(
            hr, 0,
            wpr, 1, 0,
            hproj, 0, 0, (long)Hn, 1,
            b_proj, /*relu|round|biasN*/ 7, Hn);
    }

    // 2) ent_logits (fp32 FFMA)
    ent_kernel<<<(Bn * Ln) / 8, 256>>>(hproj, W_ent, b_ent, out);

    // 3) t[z] = rtf32(P_{z/10} @ W_bil[z%10]^T)   M=512 N=768 K=768, 40 batches
    {
        dim3 grid(Hn / 128, Ln / 256, Bn * Rn);
        kB<<<grid, 512, SMEM_B_CFG>>>(
            hproj, (long)Ln * Hn,
            wbr, Rn, (long)Hn * Hn,
            tbuf, (long)Rn * Ln * Hn, (long)Ln * Hn, (long)Hn, 1,
            nullptr, /*round*/ 2, Hn);
    }

    // 4) rel[b,l,m,r] = P_b @ t[b,r]^T + b_bil[r]   M=512 N=512 K=768, 40 batches
    {
        dim3 grid(Ln / 128, Ln / 256, Bn * Rn);
        kB<<<grid, 512, SMEM_B_CFG>>>(
            hproj, (long)Ln * Hn,
            tbuf, Bn * Rn, (long)Ln * Hn,
            out + entOff, (long)Ln * Ln * Rn, 1, (long)Ln * Rn, (long)Rn,
            b_bil, /*biasZ*/ 8, Hn);
    }
}

// round 9
// speedup vs baseline: 4.4550x; 1.8770x over previous
#include <cuda_runtime.h>
#include <cuda_fp16.h>
#include <cstdint>

// Problem constants
#define Bn 4
#define Ln 512
#define Hn 768
#define En 10
#define Rn 10

// GEMM tiling: CTA 128x128, 8 warps of 64x32 (fp16 m16n8k16), BK=64 halves,
// 3-stage cp.async, (256,2) -> 2 CTAs/SM, smem 2x108KB = 216KB.
#define BM 128
#define BN 128
#define BK 64                              // halves per chunk = 128B row payload
#define NTHR 256
#define ROWB 144                           // padded row bytes (64 halves + 8 pad)
#define A_BYTES (BM * ROWB)                // 18432
#define STAGE_BYTES (2 * A_BYTES)          // 36864
#define SMEM_BYTES (3 * STAGE_BYTES)       // 110592

// ---------------- scratch (device globals: allocation-guard safe) ----------
__device__ __half g_hh[Bn * Ln * Hn];       // h -> fp16
__device__ __half g_wph[Hn * Hn];           // W_proj -> fp16
__device__ __half g_wbh[Rn * Hn * Hn];      // W_bil -> fp16
__device__ __half g_hproj[Bn * Ln * Hn];    // hproj (fp16)
__device__ __half g_t[Bn * Rn * Ln * Hn];   // t (fp16)  31.5 MB

// ---------------- helpers ----------------------------------------------------
__device__ __forceinline__ uint32_t smem_u32(const void* p) {
    uint32_t a;
    asm("{ .reg .u64 t; cvta.to.shared.u64 t, %1; cvt.u32.u64 %0, t; }" : "=r"(a) : "l"(p));
    return a;
}

__device__ __forceinline__ void cp16(uint32_t saddr, const void* g) {
    asm volatile("cp.async.cg.shared.global [%0], [%1], 16;" :: "r"(saddr), "l"(g));
}
#define CP_COMMIT() asm volatile("cp.async.commit_group;" ::: "memory")
#define CP_WAIT1()  asm volatile("cp.async.wait_group 1;" ::: "memory")

__device__ __forceinline__ void mma16(float* c, const uint32_t* a, const uint32_t* b) {
    asm volatile(
        "mma.sync.aligned.m16n8k16.row.col.f32.f16.f16.f32 "
        "{%0,%1,%2,%3}, {%4,%5,%6,%7}, {%8,%9}, {%0,%1,%2,%3};"
        : "+f"(c[0]), "+f"(c[1]), "+f"(c[2]), "+f"(c[3])
        : "r"(a[0]), "r"(a[1]), "r"(a[2]), "r"(a[3]), "r"(b[0]), "r"(b[1]));
}

__device__ __forceinline__ uint32_t lds32(uint32_t addr) {
    uint32_t v;
    asm volatile("ld.shared.b32 %0, [%1];" : "=r"(v) : "r"(addr));
    return v;
}

// ---------------- fp16 mma.sync GEMM -------------------------------------------
// C[row, col] = sum_k A[za][row,k] * B[zb][col,k]   (A,B half, K-major)
// za = z / 10, zb = z % bZmod
// C addr (elements): (z/10)*cZ1 + (z%10)*cZ2 + row*sCm + col*sCn
// mode: 1=relu, 4=bias[col], 8=bias[z%10]
// OUTHALF: store C as __half (contiguous cols, sCn==1), else float strided.
template <bool OUTHALF>
__global__ void __launch_bounds__(NTHR, 2) gemm_h(
    const __half* __restrict__ A, long sAz,
    const __half* __restrict__ B, int bZmod, long sBz,
    void* __restrict__ Cp, long cZ1, long cZ2, long sCm, long sCn,
    const float* __restrict__ bias, int mode, int K)
{
    extern __shared__ __align__(16) char smem[];
    const uint32_t sbase = smem_u32(smem);
    const int tid = threadIdx.x;
    const int z = blockIdx.z;
    const int m0 = blockIdx.y * BM;
    const int n0 = blockIdx.x * BN;
    const int nk = K / BK;   // 12

    const __half* Ag = A + (long)(z / 10) * sAz + (long)m0 * K;
    const __half* Bg = B + (long)(z % bZmod) * sBz + (long)n0 * K;

    const int wid = tid >> 5;
    const int lane = tid & 31;
    const int warp_m = wid >> 2;      // 0..1 -> 64 rows
    const int warp_n = wid & 3;       // 0..3 -> 32 cols
    const int g = lane >> 2;          // 0..7
    const int t = lane & 3;           // 0..3

    float acc[4][4][4];
#pragma unroll
    for (int mi = 0; mi < 4; ++mi)
#pragma unroll
        for (int ni = 0; ni < 4; ++ni)
#pragma unroll
            for (int q = 0; q < 4; ++q) acc[mi][ni][q] = 0.0f;

    // cp.async: 256 rows x 8 segs of 16B per stage; 8 per thread
    const int ld_row = tid >> 3;               // 0..31
    const int ld_seg = (tid & 7) * 8;          // halves: 0,8,...,56
    const __half* AgT = Ag + (long)ld_row * K + ld_seg;
    const __half* BgT = Bg + (long)ld_row * K + ld_seg;
    const uint32_t sOffT = (uint32_t)ld_row * ROWB + (uint32_t)ld_seg * 2;
    const uint32_t rowStepS = 32u * ROWB;

    auto load_stage = [&](int s, int k0) {
        const uint32_t sA = sbase + s * STAGE_BYTES + sOffT;
        const uint32_t sB = sA + A_BYTES;
#pragma unroll
        for (int it = 0; it < 4; ++it) {
            cp16(sA + it * rowStepS, AgT + (long)(it * 32) * K + k0);
            cp16(sB + it * rowStepS, BgT + (long)(it * 32) * K + k0);
        }
    };

    load_stage(0, 0); CP_COMMIT();
    if (nk > 1) load_stage(1, BK);
    CP_COMMIT();

    // fragment base byte offsets: k = 2t -> +4t bytes; k+8 -> +16 bytes
    const uint32_t aBase = (uint32_t)(warp_m * 64 + g) * ROWB + 4u * t;
    const uint32_t bBase = (uint32_t)(warp_n * 32 + g) * ROWB + 4u * t;

    for (int i = 0; i < nk; ++i) {
        CP_WAIT1();
        __syncthreads();
        if (i + 2 < nk) load_stage((i + 2) % 3, (i + 2) * BK);
        CP_COMMIT();

        const uint32_t sA = sbase + (i % 3) * STAGE_BYTES;
        const uint32_t sB = sA + A_BYTES;

#pragma unroll
        for (int ks = 0; ks < BK; ks += 16) {     // 4 k16-steps
            uint32_t af[4][4], bf[4][2];
#pragma unroll
            for (int mi = 0; mi < 4; ++mi) {
                const uint32_t p = sA + aBase + (uint32_t)(mi * 16) * ROWB + (uint32_t)ks * 2;
                af[mi][0] = lds32(p);                 // row g,   k 2t..2t+1
                af[mi][1] = lds32(p + 8 * ROWB);      // row g+8
                af[mi][2] = lds32(p + 16);            // row g,   k 2t+8..2t+9
                af[mi][3] = lds32(p + 8 * ROWB + 16);
            }
#pragma unroll
            for (int ni = 0; ni < 4; ++ni) {
                const uint32_t p = sB + bBase + (uint32_t)(ni * 8) * ROWB + (uint32_t)ks * 2;
                bf[ni][0] = lds32(p);
                bf[ni][1] = lds32(p + 16);
            }
#pragma unroll
            for (int mi = 0; mi < 4; ++mi)
#pragma unroll
                for (int ni = 0; ni < 4; ++ni)
                    mma16(acc[mi][ni], af[mi], bf[ni]);
        }
    }

    // ---------------- epilogue ----------------
    float bz = 0.0f;
    if (mode & 8) bz = bias[z % 10];
    const long czoff = (long)(z / 10) * cZ1 + (long)(z % 10) * cZ2;

#pragma unroll
    for (int mi = 0; mi < 4; ++mi) {
        const long r0 = m0 + warp_m * 64 + mi * 16 + g;
#pragma unroll
        for (int ni = 0; ni < 4; ++ni) {
            const long col = n0 + warp_n * 32 + ni * 8 + 2 * t;
            float v[4];
#pragma unroll
            for (int q = 0; q < 4; ++q) v[q] = acc[mi][ni][q];
            if (mode & 4) {
                const float b0v = bias[col], b1v = bias[col + 1];
                v[0] += b0v; v[1] += b1v; v[2] += b0v; v[3] += b1v;
            }
            if (mode & 8) { v[0] += bz; v[1] += bz; v[2] += bz; v[3] += bz; }
            if (mode & 1) {
#pragma unroll
                for (int q = 0; q < 4; ++q) v[q] = fmaxf(v[q], 0.0f);
            }
            if (OUTHALF) {
                __half* C = (__half*)Cp + czoff;
                *(__half2*)(C + r0 * sCm + col) = __floats2half2_rn(v[0], v[1]);
                *(__half2*)(C + (r0 + 8) * sCm + col) = __floats2half2_rn(v[2], v[3]);
            } else {
                float* C = (float*)Cp + czoff;
                if (sCn == 1) {
                    *(float2*)(C + r0 * sCm + col) = make_float2(v[0], v[1]);
                    *(float2*)(C + (r0 + 8) * sCm + col) = make_float2(v[2], v[3]);
                } else {
                    float* p0 = C + r0 * sCm + col * sCn;
                    float* p1 = C + (r0 + 8) * sCm + col * sCn;
                    p0[0] = v[0]; p0[sCn] = v[1];
                    p1[0] = v[2]; p1[sCn] = v[3];
                }
            }
        }
    }
}

// ---------------- fp32 -> fp16 pre-pass ---------------------------------------
__global__ void to_half(const float4* __restrict__ in, __half2* __restrict__ out, int n4) {
    int i = blockIdx.x * blockDim.x + threadIdx.x;
    if (i < n4) {
        float4 a = in[i];
        out[2 * i]     = __floats2half2_rn(a.x, a.y);
        out[2 * i + 1] = __floats2half2_rn(a.z, a.w);
    }
}

// ---------------- entity head (fp32 FFMA, tiny) -------------------------------
__global__ __launch_bounds__(256) void ent_kernel(
    const __half* __restrict__ hproj, const float* __restrict__ W_ent,
    const float* __restrict__ b_ent, float* __restrict__ out)
{
    const int warp = threadIdx.x >> 5;
    const int lane = threadIdx.x & 31;
    const int row = blockIdx.x * 8 + warp;
    const __half* hp = hproj + (long)row * Hn;

    float acc[En];
#pragma unroll
    for (int e = 0; e < En; ++e) acc[e] = 0.0f;
    for (int k = lane; k < Hn; k += 32) {
        const float hv = __half2float(hp[k]);
#pragma unroll
        for (int e = 0; e < En; ++e) acc[e] = fmaf(hv, W_ent[e * Hn + k], acc[e]);
    }
#pragma unroll
    for (int e = 0; e < En; ++e)
#pragma unroll
        for (int o = 16; o > 0; o >>= 1)
            acc[e] += __shfl_xor_sync(0xffffffffu, acc[e], o);
    if (lane == 0) {
        float* o = out + (long)row * En;
#pragma unroll
        for (int e = 0; e < En; ++e) o[e] = acc[e] + b_ent[e];
    }
}

// ---------------- host --------------------------------------------------------
extern "C" void kernel_launch(void* const* d_in, const int* in_sizes, int n_in,
                              void* d_out, int out_size)
{
    const float* h      = (const float*)d_in[0];
    const float* W_proj = (const float*)d_in[1];
    const float* b_proj = (const float*)d_in[2];
    const float* W_ent  = (const float*)d_in[3];
    const float* b_ent  = (const float*)d_in[4];
    const float* W_bil  = (const float*)d_in[5];
    const float* b_bil  = (const float*)d_in[6];
    float* out = (float*)d_out;

    __half *hh, *wph, *wbh, *hproj, *tbuf;
    cudaGetSymbolAddress((void**)&hh, g_hh);
    cudaGetSymbolAddress((void**)&wph, g_wph);
    cudaGetSymbolAddress((void**)&wbh, g_wbh);
    cudaGetSymbolAddress((void**)&hproj, g_hproj);
    cudaGetSymbolAddress((void**)&tbuf, g_t);

    cudaFuncSetAttribute(gemm_h<true>, cudaFuncAttributeMaxDynamicSharedMemorySize, SMEM_BYTES);
    cudaFuncSetAttribute(gemm_h<false>, cudaFuncAttributeMaxDynamicSharedMemorySize, SMEM_BYTES);

    // 0) convert inputs to fp16 (RN: same 10-bit mantissa rounding as tf32-rna)
    {
        int n4;
        n4 = Bn * Ln * Hn / 4;  to_half<<<(n4 + 255) / 256, 256>>>((const float4*)h, (__half2*)hh, n4);
        n4 = Hn * Hn / 4;       to_half<<<(n4 + 255) / 256, 256>>>((const float4*)W_proj, (__half2*)wph, n4);
        n4 = Rn * Hn * Hn / 4;  to_half<<<(n4 + 255) / 256, 256>>>((const float4*)W_bil, (__half2*)wbh, n4);
    }

    const long entOff = (long)Bn * Ln * En;  // 20480

    // 1) hproj(half) = relu(h @ W_proj^T + b_proj)   M=2048 N=768 K=768
    {
        dim3 grid(Hn / BN, (Bn * Ln) / BM, 1);
        gemm_h<true><<<grid, NTHR, SMEM_BYTES>>>(
            hh, 0,
            wph, 1, 0,
            hproj, 0, 0, (long)Hn, 1,
            b_proj, /*relu|biasN*/ 5, Hn);
    }

    // 2) ent_logits (fp32 FFMA)
    ent_kernel<<<(Bn * Ln) / 8, 256>>>(hproj, W_ent, b_ent, out);

    // 3) t[z](half) = P_{z/10} @ W_bil[z%10]^T   M=512 N=768 K=768, 40 batches
    {
        dim3 grid(Hn / BN, Ln / BM, Bn * Rn);
        gemm_h<true><<<grid, NTHR, SMEM_BYTES>>>(
            hproj, (long)Ln * Hn,
            wbh, Rn, (long)Hn * Hn,
            tbuf, (long)Rn * Ln * Hn, (long)Ln * Hn, (long)Hn, 1,
            nullptr, 0, Hn);
    }

    // 4) rel[b,l,m,r] = P_b @ t[b,r]^T + b_bil[r]   M=512 N=512 K=768, 40 batches
    {
        dim3 grid(Ln / BN, Ln / BM, Bn * Rn);
        gemm_h<false><<<grid, NTHR, SMEM_BYTES>>>(
            hproj, (long)Ln * Hn,
            tbuf, Bn * Rn, (long)Ln * Hn,
            out + entOff, (long)Ln * Ln * Rn, 1, (long)Ln * Rn, (long)Rn,
            b_bil, /*biasZ*/ 8, Hn);
    }
}

// round 10
// speedup vs baseline: 4.7369x; 1.0633x over previous
#include <cuda_runtime.h>
#include <cuda_fp16.h>
#include <cstdint>

// Problem constants
#define Bn 4
#define Ln 512
#define Hn 768
#define En 10
#define Rn 10

// GEMM tiling: CTA 128x128, 8 warps of 64x32 (fp16 m16n8k16), BK=64 halves,
// 3-stage cp.async, ldmatrix fragment loads, (256,2) -> 2 CTAs/SM.
#define BM 128
#define BN 128
#define BK 64
#define NTHR 256
#define ROWB 144                           // padded row bytes (64 halves + 8 pad)
#define A_BYTES (BM * ROWB)                // 18432
#define STAGE_BYTES (2 * A_BYTES)          // 36864
#define SMEM_BYTES (3 * STAGE_BYTES)       // 110592

// ---------------- scratch (device globals: allocation-guard safe) ----------
__device__ __half g_hh[Bn * Ln * Hn];       // h -> fp16
__device__ __half g_wph[Hn * Hn];           // W_proj -> fp16
__device__ __half g_wbh[Rn * Hn * Hn];      // W_bil -> fp16
__device__ __half g_hproj[Bn * Ln * Hn];    // hproj (fp16)
__device__ __half g_t[Bn * Rn * Ln * Hn];   // t (fp16)

// ---------------- helpers ----------------------------------------------------
__device__ __forceinline__ uint32_t smem_u32(const void* p) {
    uint32_t a;
    asm("{ .reg .u64 t; cvta.to.shared.u64 t, %1; cvt.u32.u64 %0, t; }" : "=r"(a) : "l"(p));
    return a;
}

__device__ __forceinline__ void cp16(uint32_t saddr, const void* g) {
    asm volatile("cp.async.cg.shared.global [%0], [%1], 16;" :: "r"(saddr), "l"(g));
}
#define CP_COMMIT() asm volatile("cp.async.commit_group;" ::: "memory")
#define CP_WAIT1()  asm volatile("cp.async.wait_group 1;" ::: "memory")

__device__ __forceinline__ void mma16(float* c, const uint32_t* a, const uint32_t* b) {
    asm volatile(
        "mma.sync.aligned.m16n8k16.row.col.f32.f16.f16.f32 "
        "{%0,%1,%2,%3}, {%4,%5,%6,%7}, {%8,%9}, {%0,%1,%2,%3};"
        : "+f"(c[0]), "+f"(c[1]), "+f"(c[2]), "+f"(c[3])
        : "r"(a[0]), "r"(a[1]), "r"(a[2]), "r"(a[3]), "r"(b[0]), "r"(b[1]));
}

__device__ __forceinline__ void ldsm4(uint32_t& r0, uint32_t& r1, uint32_t& r2, uint32_t& r3,
                                      uint32_t addr) {
    asm volatile("ldmatrix.sync.aligned.m8n8.x4.shared.b16 {%0,%1,%2,%3}, [%4];"
                 : "=r"(r0), "=r"(r1), "=r"(r2), "=r"(r3) : "r"(addr));
}

// ---------------- fp16 mma.sync GEMM -------------------------------------------
// C[row, col] = sum_k A[za][row,k] * B[zb][col,k]   (A,B half, K-major)
// za = z / 10, zb = z % bZmod
// C addr (elements): (z/10)*cZ1 + (z%10)*cZ2 + row*sCm + col*sCn
// mode: 1=relu, 4=bias[col], 8=bias[z%10]
template <bool OUTHALF>
__global__ void __launch_bounds__(NTHR, 2) gemm_h(
    const __half* __restrict__ A, long sAz,
    const __half* __restrict__ B, int bZmod, long sBz,
    void* __restrict__ Cp, long cZ1, long cZ2, long sCm, long sCn,
    const float* __restrict__ bias, int mode, int K)
{
    extern __shared__ __align__(16) char smem[];
    const uint32_t sbase = smem_u32(smem);
    const int tid = threadIdx.x;
    const int z = blockIdx.z;
    const int m0 = blockIdx.y * BM;
    const int n0 = blockIdx.x * BN;
    const int nk = K / BK;   // 12

    const __half* Ag = A + (long)(z / 10) * sAz + (long)m0 * K;
    const __half* Bg = B + (long)(z % bZmod) * sBz + (long)n0 * K;

    const int wid = tid >> 5;
    const int lane = tid & 31;
    const int warp_m = wid >> 2;      // 0..1 -> 64 rows
    const int warp_n = wid & 3;       // 0..3 -> 32 cols
    const int g = lane >> 2;          // 0..7
    const int t = lane & 3;           // 0..3

    float acc[4][4][4];
#pragma unroll
    for (int mi = 0; mi < 4; ++mi)
#pragma unroll
        for (int ni = 0; ni < 4; ++ni)
#pragma unroll
            for (int q = 0; q < 4; ++q) acc[mi][ni][q] = 0.0f;

    // cp.async: 256 rows x 8 segs of 16B per stage; 8 per thread
    const int ld_row = tid >> 3;               // 0..31
    const int ld_seg = (tid & 7) * 8;          // halves
    const __half* AgT = Ag + (long)ld_row * K + ld_seg;
    const __half* BgT = Bg + (long)ld_row * K + ld_seg;
    const uint32_t sOffT = (uint32_t)ld_row * ROWB + (uint32_t)ld_seg * 2;
    const uint32_t rowStepS = 32u * ROWB;

    auto load_stage = [&](int s, int k0) {
        const uint32_t sA = sbase + s * STAGE_BYTES + sOffT;
        const uint32_t sB = sA + A_BYTES;
#pragma unroll
        for (int it = 0; it < 4; ++it) {
            cp16(sA + it * rowStepS, AgT + (long)(it * 32) * K + k0);
            cp16(sB + it * rowStepS, BgT + (long)(it * 32) * K + k0);
        }
    };

    load_stage(0, 0); CP_COMMIT();
    if (nk > 1) load_stage(1, BK);
    CP_COMMIT();

    // ldmatrix per-thread base addresses (byte offsets into stage):
    // A x4: matrices {rows 0-7 klo, rows 8-15 klo, rows 0-7 khi, rows 8-15 khi}
    //   thread i -> row (i&15), khalf (i>>4): addr = (row)*ROWB + khalf*16
    const uint32_t aBaseT = (uint32_t)(warp_m * 64 + (lane & 15)) * ROWB + (uint32_t)(lane >> 4) * 16;
    // B x4: matrices {ni0 klo, ni0 khi, ni1 klo, ni1 khi}
    //   thread i: m=i>>3; row=(i&7); ni_off=(m>>1)*8; khalf=(m&1)
    const uint32_t bBaseT = (uint32_t)(warp_n * 32 + ((lane >> 4) << 3) + (lane & 7)) * ROWB
                          + (uint32_t)((lane >> 3) & 1) * 16;

    for (int i = 0; i < nk; ++i) {
        CP_WAIT1();
        __syncthreads();
        if (i + 2 < nk) load_stage((i + 2) % 3, (i + 2) * BK);
        CP_COMMIT();

        const uint32_t sA = sbase + (i % 3) * STAGE_BYTES;
        const uint32_t sB = sA + A_BYTES;

#pragma unroll
        for (int ks = 0; ks < BK; ks += 16) {     // 4 k16-steps
            uint32_t af[4][4], bf[4][2];
#pragma unroll
            for (int mi = 0; mi < 4; ++mi)
                ldsm4(af[mi][0], af[mi][1], af[mi][2], af[mi][3],
                      sA + aBaseT + (uint32_t)(mi * 16) * ROWB + (uint32_t)ks * 2);
            // B: two x4 loads cover ni {0,1} and {2,3}
            ldsm4(bf[0][0], bf[0][1], bf[1][0], bf[1][1],
                  sB + bBaseT + (uint32_t)ks * 2);
            ldsm4(bf[2][0], bf[2][1], bf[3][0], bf[3][1],
                  sB + bBaseT + 16u * ROWB + (uint32_t)ks * 2);
#pragma unroll
            for (int mi = 0; mi < 4; ++mi)
#pragma unroll
                for (int ni = 0; ni < 4; ++ni)
                    mma16(acc[mi][ni], af[mi], bf[ni]);
        }
    }

    // ---------------- epilogue ----------------
    float bz = 0.0f;
    if (mode & 8) bz = bias[z % 10];
    const long czoff = (long)(z / 10) * cZ1 + (long)(z % 10) * cZ2;

#pragma unroll
    for (int mi = 0; mi < 4; ++mi) {
        const long r0 = m0 + warp_m * 64 + mi * 16 + g;
#pragma unroll
        for (int ni = 0; ni < 4; ++ni) {
            const long col = n0 + warp_n * 32 + ni * 8 + 2 * t;
            float v[4];
#pragma unroll
            for (int q = 0; q < 4; ++q) v[q] = acc[mi][ni][q];
            if (mode & 4) {
                const float b0v = bias[col], b1v = bias[col + 1];
                v[0] += b0v; v[1] += b1v; v[2] += b0v; v[3] += b1v;
            }
            if (mode & 8) { v[0] += bz; v[1] += bz; v[2] += bz; v[3] += bz; }
            if (mode & 1) {
#pragma unroll
                for (int q = 0; q < 4; ++q) v[q] = fmaxf(v[q], 0.0f);
            }
            if (OUTHALF) {
                __half* C = (__half*)Cp + czoff;
                *(__half2*)(C + r0 * sCm + col) = __floats2half2_rn(v[0], v[1]);
                *(__half2*)(C + (r0 + 8) * sCm + col) = __floats2half2_rn(v[2], v[3]);
            } else {
                float* C = (float*)Cp + czoff;
                if (sCn == 1) {
                    *(float2*)(C + r0 * sCm + col) = make_float2(v[0], v[1]);
                    *(float2*)(C + (r0 + 8) * sCm + col) = make_float2(v[2], v[3]);
                } else {
                    float* p0 = C + r0 * sCm + col * sCn;
                    float* p1 = C + (r0 + 8) * sCm + col * sCn;
                    p0[0] = v[0]; p0[sCn] = v[1];
                    p1[0] = v[2]; p1[sCn] = v[3];
                }
            }
        }
    }
}

// ---------------- fp32 -> fp16 pre-pass ---------------------------------------
__global__ void to_half(const float4* __restrict__ in, __half2* __restrict__ out, int n4) {
    int i = blockIdx.x * blockDim.x + threadIdx.x;
    if (i < n4) {
        float4 a = in[i];
        out[2 * i]     = __floats2half2_rn(a.x, a.y);
        out[2 * i + 1] = __floats2half2_rn(a.z, a.w);
    }
}

// ---------------- entity head (fp32 FFMA, tiny) -------------------------------
__global__ __launch_bounds__(256) void ent_kernel(
    const __half* __restrict__ hproj, const float* __restrict__ W_ent,
    const float* __restrict__ b_ent, float* __restrict__ out)
{
    const int warp = threadIdx.x >> 5;
    const int lane = threadIdx.x & 31;
    const int row = blockIdx.x * 8 + warp;
    const __half* hp = hproj + (long)row * Hn;

    float acc[En];
#pragma unroll
    for (int e = 0; e < En; ++e) acc[e] = 0.0f;
    for (int k = lane; k < Hn; k += 32) {
        const float hv = __half2float(hp[k]);
#pragma unroll
        for (int e = 0; e < En; ++e) acc[e] = fmaf(hv, W_ent[e * Hn + k], acc[e]);
    }
#pragma unroll
    for (int e = 0; e < En; ++e)
#pragma unroll
        for (int o = 16; o > 0; o >>= 1)
            acc[e] += __shfl_xor_sync(0xffffffffu, acc[e], o);
    if (lane == 0) {
        float* o = out + (long)row * En;
#pragma unroll
        for (int e = 0; e < En; ++e) o[e] = acc[e] + b_ent[e];
    }
}

// ---------------- host --------------------------------------------------------
extern "C" void kernel_launch(void* const* d_in, const int* in_sizes, int n_in,
                              void* d_out, int out_size)
{
    const float* h      = (const float*)d_in[0];
    const float* W_proj = (const float*)d_in[1];
    const float* b_proj = (const float*)d_in[2];
    const float* W_ent  = (const float*)d_in[3];
    const float* b_ent  = (const float*)d_in[4];
    const float* W_bil  = (const float*)d_in[5];
    const float* b_bil  = (const float*)d_in[6];
    float* out = (float*)d_out;

    __half *hh, *wph, *wbh, *hproj, *tbuf;
    cudaGetSymbolAddress((void**)&hh, g_hh);
    cudaGetSymbolAddress((void**)&wph, g_wph);
    cudaGetSymbolAddress((void**)&wbh, g_wbh);
    cudaGetSymbolAddress((void**)&hproj, g_hproj);
    cudaGetSymbolAddress((void**)&tbuf, g_t);

    cudaFuncSetAttribute(gemm_h<true>, cudaFuncAttributeMaxDynamicSharedMemorySize, SMEM_BYTES);
    cudaFuncSetAttribute(gemm_h<false>, cudaFuncAttributeMaxDynamicSharedMemorySize, SMEM_BYTES);

    // 0) convert inputs to fp16 (RN: same 10-bit mantissa rounding as tf32-rna)
    {
        int n4;
        n4 = Bn * Ln * Hn / 4;  to_half<<<(n4 + 255) / 256, 256>>>((const float4*)h, (__half2*)hh, n4);
        n4 = Hn * Hn / 4;       to_half<<<(n4 + 255) / 256, 256>>>((const float4*)W_proj, (__half2*)wph, n4);
        n4 = Rn * Hn * Hn / 4;  to_half<<<(n4 + 255) / 256, 256>>>((const float4*)W_bil, (__half2*)wbh, n4);
    }

    const long entOff = (long)Bn * Ln * En;  // 20480

    // 1) hproj(half) = relu(h @ W_proj^T + b_proj)   M=2048 N=768 K=768
    {
        dim3 grid(Hn / BN, (Bn * Ln) / BM, 1);
        gemm_h<true><<<grid, NTHR, SMEM_BYTES>>>(
            hh, 0,
            wph, 1, 0,
            hproj, 0, 0, (long)Hn, 1,
            b_proj, /*relu|biasN*/ 5, Hn);
    }

    // 2) ent_logits (fp32 FFMA)
    ent_kernel<<<(Bn * Ln) / 8, 256>>>(hproj, W_ent, b_ent, out);

    // 3) t[z](half) = P_{z/10} @ W_bil[z%10]^T   M=512 N=768 K=768, 40 batches
    {
        dim3 grid(Hn / BN, Ln / BM, Bn * Rn);
        gemm_h<true><<<grid, NTHR, SMEM_BYTES>>>(
            hproj, (long)Ln * Hn,
            wbh, Rn, (long)Hn * Hn,
            tbuf, (long)Rn * Ln * Hn, (long)Ln * Hn, (long)Hn, 1,
            nullptr, 0, Hn);
    }

    // 4) rel[b,l,m,r] = P_b @ t[b,r]^T + b_bil[r]   M=512 N=512 K=768, 40 batches
    {
        dim3 grid(Ln / BN, Ln / BM, Bn * Rn);
        gemm_h<false><<<grid, NTHR, SMEM_BYTES>>>(
            hproj, (long)Ln * Hn,
            tbuf, Bn * Rn, (long)Ln * Hn,
            out + entOff, (long)Ln * Ln * Rn, 1, (long)Ln * Rn, (long)Rn,
            b_bil, /*biasZ*/ 8, Hn);
    }
}